// round 3
// baseline (speedup 1.0000x reference)
#include <cuda_runtime.h>

// ---------------------------------------------------------------------------
// Talking-heads MHSA, B=2 P=2048 H=8 DF=32, fp32.
//   k1: QKV = x @ Wqkv^T -> g_q (pre-scaled), g_k, g_v   [B,H,P,32]
//   k2: fused attention, 512 thr/CTA, 2 split-K copies w/ named barriers
//   k3: out = ctxt @ Wproj^T
// ---------------------------------------------------------------------------

#define DEV_INLINE __device__ __forceinline__

struct U64F2 { union { unsigned long long u; float2 f; }; };

DEV_INLINE U64F2 f2fma(U64F2 a, U64F2 b, U64F2 c) {
    U64F2 d;
    asm("fma.rn.f32x2 %0, %1, %2, %3;" : "=l"(d.u) : "l"(a.u), "l"(b.u), "l"(c.u));
    return d;
}
DEV_INLINE U64F2 f2mul(U64F2 a, U64F2 b) {
    U64F2 d;
    asm("mul.rn.f32x2 %0, %1, %2;" : "=l"(d.u) : "l"(a.u), "l"(b.u));
    return d;
}
DEV_INLINE U64F2 pk2(float v) {
    U64F2 d;
    asm("mov.b64 %0, {%1, %1};" : "=l"(d.u) : "f"(v));
    return d;
}

constexpr int Bc = 2, Pc = 2048, Hc = 8, DFc = 32;
constexpr float QSCALE = 0.17677669529663687f;  // 1/sqrt(32)

__device__ float g_q[Bc * Hc * Pc * DFc];
__device__ float g_k[Bc * Hc * Pc * DFc];
__device__ float g_v[Bc * Hc * Pc * DFc];
__device__ float g_ctxt[Bc * Pc * Hc * DFc];

// ---------------------------------------------------------------------------
// GEMM: C[M,N] = A[M,K] @ Bw[N,K]^T (unchanged from R2)
// ---------------------------------------------------------------------------
template <int EPI>
__global__ __launch_bounds__(256) void gemm_nt(const float* __restrict__ A,
                                               const float* __restrict__ Bw,
                                               float* __restrict__ C,
                                               int M, int N, int K) {
    __shared__ __align__(16) float As[64][68];
    __shared__ __align__(16) float Bs[64][68];

    const int tid = threadIdx.x;
    const int tx = tid & 15, ty = tid >> 4;
    const int m0 = blockIdx.x << 6, n0 = blockIdx.y << 6;
    const int bn = tid & 63;
    const int bk = (tid >> 6) << 4;

    U64F2 acc[4][2];
#pragma unroll
    for (int i = 0; i < 4; i++) {
        acc[i][0].f = make_float2(0.f, 0.f);
        acc[i][1].f = make_float2(0.f, 0.f);
    }

    for (int kc = 0; kc < K; kc += 64) {
#pragma unroll
        for (int i = 0; i < 4; i++) {
            int v = tid + (i << 8);
            int r = v >> 4, k4 = v & 15;
            *(float4*)&As[r][k4 << 2] =
                *(const float4*)&A[(size_t)(m0 + r) * K + kc + (k4 << 2)];
        }
#pragma unroll
        for (int c4 = 0; c4 < 4; c4++) {
            float4 bv =
                *(const float4*)&Bw[(size_t)(n0 + bn) * K + kc + bk + (c4 << 2)];
            Bs[bk + (c4 << 2) + 0][bn] = bv.x;
            Bs[bk + (c4 << 2) + 1][bn] = bv.y;
            Bs[bk + (c4 << 2) + 2][bn] = bv.z;
            Bs[bk + (c4 << 2) + 3][bn] = bv.w;
        }
        __syncthreads();
#pragma unroll 8
        for (int kk = 0; kk < 64; kk++) {
            float4 b01 = *(const float4*)&Bs[kk][tx << 2];
            U64F2 b0, b1;
            b0.f = make_float2(b01.x, b01.y);
            b1.f = make_float2(b01.z, b01.w);
#pragma unroll
            for (int i = 0; i < 4; i++) {
                U64F2 a2 = pk2(As[(ty << 2) + i][kk]);
                acc[i][0] = f2fma(a2, b0, acc[i][0]);
                acc[i][1] = f2fma(a2, b1, acc[i][1]);
            }
        }
        __syncthreads();
    }

    if (EPI == 0) {
#pragma unroll
        for (int i = 0; i < 4; i++) {
            float4 vout;
            vout.x = acc[i][0].f.x; vout.y = acc[i][0].f.y;
            vout.z = acc[i][1].f.x; vout.w = acc[i][1].f.y;
            *(float4*)&C[(size_t)(m0 + (ty << 2) + i) * N + n0 + (tx << 2)] = vout;
        }
    } else {
#pragma unroll
        for (int i = 0; i < 4; i++) {
            float vals[4] = {acc[i][0].f.x, acc[i][0].f.y, acc[i][1].f.x, acc[i][1].f.y};
            int r = m0 + (ty << 2) + i;
            int bb = r >> 11, p = r & 2047;
#pragma unroll
            for (int j = 0; j < 4; j++) {
                int c = n0 + (tx << 2) + j;
                int sgrp = c >> 8;
                int h = (c >> 5) & 7, d = c & 31;
                int idx = ((bb * Hc + h) * Pc + p) * DFc + d;
                if (sgrp == 0)      g_q[idx] = vals[j] * QSCALE;
                else if (sgrp == 1) g_k[idx] = vals[j];
                else                g_v[idx] = vals[j];
            }
        }
    }
}

// ---------------------------------------------------------------------------
// Fused talking-heads attention. 512 threads; warps 0-7 = copy 0 (even key
// tiles), warps 8-15 = copy 1 (odd key tiles). Per-copy named barriers.
// Within a copy: warp = head h (also output head g), lane = query row.
// ---------------------------------------------------------------------------
struct AttnSmem {
    float Ks[2][8][32][36];  // K tile (stride 36); reused as Bs[8][32][33] bias/scores
    float Vs[2][8][32][32];
    float SP[2][8][32][32];  // raw scores, layout [h][kq][p]
    float ml1[8][32][2];     // copy 1 (m,l) for the final merge
};

DEV_INLINE void barC(int s) {
    asm volatile("bar.sync %0, %1;" :: "r"(s + 1), "r"(256) : "memory");
}

__global__ __launch_bounds__(512, 1) void attn_fused(const float* __restrict__ bias,
                                                     const float* __restrict__ wtalk) {
    extern __shared__ char smem_raw[];
    AttnSmem& sm = *reinterpret_cast<AttnSmem*>(smem_raw);

    const int b = blockIdx.x & 1;
    const int p0 = (blockIdx.x >> 1) * 32;
    const int tid = threadIdx.x;
    const int warp = tid >> 5, lane = tid & 31;
    const int s = warp >> 3;      // copy index
    const int h = warp & 7;       // head (= output head g)
    const int tloc = tid & 255;   // thread id within copy
    const int srow = tloc >> 3, sd4 = tloc & 7;  // staging row / float4-chunk

    float wv[8];
#pragma unroll
    for (int hh = 0; hh < 8; hh++) wv[hh] = wtalk[h * 8 + hh];

    // Q rows (head h, query p0+lane), pre-scaled (identical in both copies).
    U64F2 q[16];
    {
        const float4* qp =
            (const float4*)&g_q[((size_t)(b * Hc + h) * Pc + p0 + lane) * DFc];
#pragma unroll
        for (int i = 0; i < 8; i++) {
            float4 v = qp[i];
            q[2 * i].f     = make_float2(v.x, v.y);
            q[2 * i + 1].f = make_float2(v.z, v.w);
        }
    }
    U64F2 o[16];
#pragma unroll
    for (int i = 0; i < 16; i++) o[i].f = make_float2(0.f, 0.f);
    float m_run = -1e30f, l_run = 0.f;

    const float4* kb4 = (const float4*)&g_k[(size_t)b * Hc * Pc * DFc];
    const float4* vb4 = (const float4*)&g_v[(size_t)b * Hc * Pc * DFc];
    const float4* bias4 = (const float4*)bias;

    float* bs = &sm.Ks[s][0][0][0];  // bias/mixed-score overlay, stride 33

    // prefetch first bias tile: chunk i -> (head i, row srow, d4 sd4)
    float4 breg[8];
    {
        const int kq0 = s * 32;
#pragma unroll
        for (int i = 0; i < 8; i++)
            breg[i] = bias4[(size_t)(i * Pc + p0 + srow) * (Pc / 4) + (kq0 >> 2) + sd4];
    }

    for (int tt = 0; tt < 32; tt++) {
        const int kq0 = (tt * 2 + s) * 32;

        // ---- stage K (stride 36), V (stride 32) ----
#pragma unroll
        for (int i = 0; i < 8; i++) {
            float4 kv = kb4[(size_t)(i * Pc + kq0 + srow) * 8 + sd4];
            float4 vv = vb4[(size_t)(i * Pc + kq0 + srow) * 8 + sd4];
            *(float4*)&sm.Ks[s][i][srow][sd4 << 2] = kv;
            *(float4*)&sm.Vs[s][i][srow][sd4 << 2] = vv;
        }
        barC(s);

        // ---- phase 1: S[h][kq][p=lane] = q . k ----
        {
            const float4* kbase = (const float4*)&sm.Ks[s][h][0][0];
#pragma unroll 4
            for (int kq = 0; kq < 32; kq++) {
                const float4* kp = kbase + kq * 9;
                U64F2 a0, a1, a2, a3;
                a0.f = make_float2(0.f, 0.f); a1.f = a0.f; a2.f = a0.f; a3.f = a0.f;
#pragma unroll
                for (int j = 0; j < 8; j += 2) {
                    float4 k0 = kp[j], k1 = kp[j + 1];
                    U64F2 t0, t1, t2, t3;
                    t0.f = make_float2(k0.x, k0.y);
                    t1.f = make_float2(k0.z, k0.w);
                    t2.f = make_float2(k1.x, k1.y);
                    t3.f = make_float2(k1.z, k1.w);
                    a0 = f2fma(q[2 * j],     t0, a0);
                    a1 = f2fma(q[2 * j + 1], t1, a1);
                    a2 = f2fma(q[2 * j + 2], t2, a2);
                    a3 = f2fma(q[2 * j + 3], t3, a3);
                }
                sm.SP[s][h][kq][lane] =
                    (a0.f.x + a0.f.y) + (a1.f.x + a1.f.y) +
                    ((a2.f.x + a2.f.y) + (a3.f.x + a3.f.y));
            }
        }
        barC(s);  // K tile now dead -> overlay bias

        // ---- dump prefetched bias into overlay, prefetch next ----
#pragma unroll
        for (int i = 0; i < 8; i++) {
            float* dst = &bs[(i * 32 + srow) * 33 + (sd4 << 2)];
            dst[0] = breg[i].x; dst[1] = breg[i].y;
            dst[2] = breg[i].z; dst[3] = breg[i].w;
        }
        if (tt != 31) {
            const int kqn = kq0 + 64;
#pragma unroll
            for (int i = 0; i < 8; i++)
                breg[i] =
                    bias4[(size_t)(i * Pc + p0 + srow) * (Pc / 4) + (kqn >> 2) + sd4];
        }
        barC(s);

        // ---- passA: talking-heads mix + bias (in place), track max ----
        float mt = m_run;
        {
            float* trow = &bs[(h * 32 + lane) * 33];
#pragma unroll 4
            for (int kq = 0; kq < 32; kq++) {
                float tv = trow[kq];
#pragma unroll
                for (int hh = 0; hh < 8; hh++)
                    tv = fmaf(wv[hh], sm.SP[s][hh][kq][lane], tv);
                trow[kq] = tv;
                mt = fmaxf(mt, tv);
            }
        }
        float sc = __expf(m_run - mt);
        m_run = mt;
        l_run *= sc;
        {
            U64F2 sc2 = pk2(sc);
#pragma unroll
            for (int j = 0; j < 16; j++) o[j] = f2mul(o[j], sc2);
        }

        // ---- fused exp + P@V ----
        {
            const float* trow = &bs[(h * 32 + lane) * 33];
            const float4* vb = (const float4*)&sm.Vs[s][h][0][0];
#pragma unroll 2
            for (int kq = 0; kq < 32; kq++) {
                float e = __expf(trow[kq] - mt);
                l_run += e;
                U64F2 pr2 = pk2(e);
                const float4* vp = vb + (kq << 3);
#pragma unroll
                for (int j = 0; j < 8; j++) {
                    float4 vv = vp[j];
                    U64F2 vlo, vhi;
                    vlo.f = make_float2(vv.x, vv.y);
                    vhi.f = make_float2(vv.z, vv.w);
                    o[2 * j]     = f2fma(pr2, vlo, o[2 * j]);
                    o[2 * j + 1] = f2fma(pr2, vhi, o[2 * j + 1]);
                }
            }
        }
        barC(s);  // protect Ks/Vs/SP for next tile
    }

    // ---- merge the two copies ----
    __syncthreads();
    if (s == 1) {
        sm.ml1[h][lane][0] = m_run;
        sm.ml1[h][lane][1] = l_run;
        float* ob = &sm.Ks[1][h][lane][0];  // copy-1 K area as o-buffer (stride 36)
#pragma unroll
        for (int i = 0; i < 8; i++) {
            float4 v;
            v.x = o[2 * i].f.x;     v.y = o[2 * i].f.y;
            v.z = o[2 * i + 1].f.x; v.w = o[2 * i + 1].f.y;
            *(float4*)&ob[i << 2] = v;
        }
    }
    __syncthreads();
    if (s == 0) {
        float m1 = sm.ml1[h][lane][0], l1 = sm.ml1[h][lane][1];
        float m = fmaxf(m_run, m1);
        float e0 = __expf(m_run - m), e1 = __expf(m1 - m);
        float linv = 1.0f / (l_run * e0 + l1 * e1);
        const float* ob = &sm.Ks[1][h][lane][0];
        float* outp = &g_ctxt[((size_t)(b * Pc + p0 + lane) * (Hc * DFc)) + h * DFc];
        U64F2 c0 = pk2(e0 * linv), c1 = pk2(e1 * linv);
#pragma unroll
        for (int i = 0; i < 8; i++) {
            float4 o1v = *(const float4*)&ob[i << 2];
            U64F2 lo, hi, b0, b1;
            b0.f = make_float2(o1v.x, o1v.y);
            b1.f = make_float2(o1v.z, o1v.w);
            lo = f2fma(c1, b0, f2mul(o[2 * i], c0));
            hi = f2fma(c1, b1, f2mul(o[2 * i + 1], c0));
            float4 v;
            v.x = lo.f.x; v.y = lo.f.y; v.z = hi.f.x; v.w = hi.f.y;
            ((float4*)outp)[i] = v;
        }
    }
}

// ---------------------------------------------------------------------------
extern "C" void kernel_launch(void* const* d_in, const int* in_sizes, int n_in,
                              void* d_out, int out_size) {
    (void)in_sizes; (void)n_in; (void)out_size;
    const float* x     = (const float*)d_in[0];
    const float* bias  = (const float*)d_in[1];
    const float* wqkv  = (const float*)d_in[2];
    const float* wtalk = (const float*)d_in[3];
    const float* wproj = (const float*)d_in[4];
    float* out = (float*)d_out;

    cudaFuncSetAttribute(attn_fused, cudaFuncAttributeMaxDynamicSharedMemorySize,
                         (int)sizeof(AttnSmem));

    void* ctxt_ptr = nullptr;
    cudaGetSymbolAddress(&ctxt_ptr, g_ctxt);

    gemm_nt<1><<<dim3(64, 12), 256>>>(x, wqkv, nullptr, Bc * Pc, 3 * Hc * DFc, 128);

    attn_fused<<<(Pc / 32) * Bc, 512, sizeof(AttnSmem)>>>(bias, wtalk);

    gemm_nt<0><<<dim3(64, 2), 256>>>((const float*)ctxt_ptr, wproj, out,
                                     Bc * Pc, 128, Hc * DFc);
}